// round 15
// baseline (speedup 1.0000x reference)
#include <cuda_runtime.h>

// ---------------------------------------------------------------------------
// NCC plane-sweep forward (B=1, N=4, H=160, W=192, patch 5x5, 9 depth taps,
// depth dilation 2). Arithmetic FROZEN (bit-exact vs reference since R9):
//   PP=K·R: FMA-ascending; Hmat chain: mul+add; tap matvec: FMA-ascending;
//   all divides IEEE div.rn; reductions mul+add; view sum sequential.
// R14 (scheduling only):
//   - tap loop fully predicated (no break): 25-way ILP on FMA/MUFU, MLP=25
//     on gathers; masked taps follow reference exactly (coords->0, gather
//     dst[0], samp=0)
//   - per-(pix,d) dp/nv hoisted into init kernel as float4 table (1 LDG.128
//     instead of 4 scattered LDG x 4 views)
// ---------------------------------------------------------------------------

namespace cfg {
constexpr int H = 160;
constexpr int W = 192;
constexpr int NVIEW = 4;
constexpr int DS = 9;
constexpr int DIL = 2;
constexpr int PS = 25;
constexpr int HW = H * W;
constexpr float THR = 0.5f;
}

__device__ float g_PP[cfg::NVIEW][9];    // K * R
__device__ float g_K0[cfg::NVIEW][9];    // K^-1 (Ks[:, :, 0])
__device__ float g_T[cfg::NVIEW][3];
__device__ float g_smean[cfg::HW];
__device__ float g_svar[cfg::HW];
__device__ float4 g_tap[cfg::DS * cfg::HW];     // (dp, nv0, nv1, nv2)
// staging: scores [DS][HW] as float4 (one lane per view); masks as u32/4B
__device__ float4   g_vs4[cfg::DS * cfg::HW];
__device__ unsigned g_mb4[cfg::DS * cfg::HW];

__device__ __forceinline__ int perm_d(int d) {
    return (d == 0) ? 4 : (d == 4) ? 0 : d;
}

// Plain mul+add sequential chain (no FMA)
__device__ __forceinline__ float dot3m(float a0, float b0, float a1, float b1,
                                       float a2, float b2) {
    return __fadd_rn(__fadd_rn(__fmul_rn(a0, b0), __fmul_rn(a1, b1)),
                     __fmul_rn(a2, b2));
}

// Ascending FMA chain, zero init
__device__ __forceinline__ float dot3f(float a0, float b0, float a1, float b1,
                                       float a2, float b2) {
    return fmaf(a2, b2, fmaf(a1, b1, __fmul_rn(a0, b0)));
}

// ---------------------------------------------------------------------------
// grid.y == 0 : camera constants (block 0) + per-pixel src stats
// grid.y >= 1 : per-(pix, d=y-1) tap table (dp, nv) with zero padding
__global__ void __launch_bounds__(256)
init_kernel(const float* __restrict__ src,
            const float* __restrict__ Ks,
            const float* __restrict__ Rs,
            const float* __restrict__ Ts,
            const float* __restrict__ depth,
            const float* __restrict__ norm) {
    using namespace cfg;
    int pix = blockIdx.x * blockDim.x + threadIdx.x;

    if (blockIdx.y == 0) {
        if (blockIdx.x == 0 && threadIdx.x < NVIEW) {
            int n = threadIdx.x;
            const float* Ki = Ks + n * 18;       // Ks[0,n,0] = K^-1
            const float* K  = Ks + n * 18 + 9;   // Ks[0,n,1] = K
            const float* R  = Rs + n * 9;
#pragma unroll
            for (int i = 0; i < 3; i++)
#pragma unroll
                for (int j = 0; j < 3; j++)
                    g_PP[n][i * 3 + j] = dot3f(K[i * 3 + 0], R[0 * 3 + j],
                                               K[i * 3 + 1], R[1 * 3 + j],
                                               K[i * 3 + 2], R[2 * 3 + j]);
#pragma unroll
            for (int i = 0; i < 9; i++) g_K0[n][i] = Ki[i];
#pragma unroll
            for (int i = 0; i < 3; i++) g_T[n][i] = Ts[n * 3 + i];
        }
        if (pix >= HW) return;
        int h = pix / W;
        int w = pix - h * W;

        float sp[PS];
        float ssum = 0.f;
#pragma unroll
        for (int p = 0; p < PS; p++) {
            int hh = h + p / 5 - 2, ww = w + p % 5 - 2;
            float v = 0.f;
            if (hh >= 0 && hh < H && ww >= 0 && ww < W) v = src[hh * W + ww];
            sp[p] = v;
            ssum = __fadd_rn(ssum, v);
        }
        float smean = __fdiv_rn(ssum, 25.f);
        float svar = 0.f;
#pragma unroll
        for (int p = 0; p < PS; p++) {
            float scv = __fsub_rn(sp[p], smean);
            svar = __fadd_rn(svar, __fmul_rn(scv, scv));
        }
        g_smean[pix] = smean;
        g_svar[pix]  = __fdiv_rn(svar, 25.f);
        return;
    }

    if (pix >= HW) return;
    const int d = blockIdx.y - 1;
    const int h = pix / W;
    const int w = pix - h * W;
    const int pd = perm_d(d);
    const int pi = pd / 3 - 1;
    const int pj = pd % 3 - 1;

    int hd = h + DIL * pi, wd = w + DIL * pj;
    float dp = 0.f;
    if (hd >= 0 && hd < H && wd >= 0 && wd < W) dp = depth[hd * W + wd];

    int hn = h + pi, wn = w + pj;
    float nv0 = 0.f, nv1 = 0.f, nv2 = 0.f;
    if (hn >= 0 && hn < H && wn >= 0 && wn < W) {
        int o = hn * W + wn;
        nv0 = norm[o];
        nv1 = norm[HW + o];
        nv2 = norm[2 * HW + o];
    }
    g_tap[d * HW + pix] = make_float4(dp, nv0, nv1, nv2);
}

// ---------------------------------------------------------------------------
// One thread per (pixel, depth tap d [grid.y], view n [grid.z]).
__global__ void __launch_bounds__(256)
ncc_view_kernel(const float* __restrict__ src,
                const float* __restrict__ dst) {
    using namespace cfg;
    const int pix = blockIdx.x * blockDim.x + threadIdx.x;
    if (pix >= HW) return;
    const int d = blockIdx.y;
    const int n = blockIdx.z;
    const int h = pix / W;
    const int w = pix - h * W;

    float* vs_out = reinterpret_cast<float*>(&g_vs4[d * HW + pix]) + n;
    unsigned char* mb_out =
        reinterpret_cast<unsigned char*>(&g_mb4[d * HW + pix]) + n;

    const float4 tap = g_tap[d * HW + pix];
    const float dp  = tap.x;
    const float nv0 = tap.y, nv1 = tap.z, nv2 = tap.w;

    bool valid_dn = (dp > 0.f) && (nv2 < 0.f);
    bool interior = (h >= 2) && (h < H - 2) && (w >= 2) && (w < W - 2);

    if (!interior || !valid_dn) {   // any src tap OOB / invalid -> mall=false
        *vs_out = THR;
        *mb_out = 0;
        return;
    }

    const float dsafe = dp;  // dp > 0 here

    // m = I - (T_i * n_j) / dsafe  (entry-wise IEEE ops)
    float mM[9];
#pragma unroll
    for (int i = 0; i < 3; i++) {
        float Ti = g_T[n][i];
        float q0 = __fdiv_rn(__fmul_rn(Ti, nv0), dsafe);
        float q1 = __fdiv_rn(__fmul_rn(Ti, nv1), dsafe);
        float q2 = __fdiv_rn(__fmul_rn(Ti, nv2), dsafe);
        mM[i * 3 + 0] = __fsub_rn((i == 0) ? 1.f : 0.f, q0);
        mM[i * 3 + 1] = __fsub_rn((i == 1) ? 1.f : 0.f, q1);
        mM[i * 3 + 2] = __fsub_rn((i == 2) ? 1.f : 0.f, q2);
    }
    // tmp = PP @ m ; Hm = tmp @ K0  (mul+add chains)
    float tmp[9], Hm[9];
#pragma unroll
    for (int i = 0; i < 3; i++)
#pragma unroll
        for (int k = 0; k < 3; k++)
            tmp[i * 3 + k] = dot3m(g_PP[n][i * 3 + 0], mM[0 * 3 + k],
                                   g_PP[n][i * 3 + 1], mM[1 * 3 + k],
                                   g_PP[n][i * 3 + 2], mM[2 * 3 + k]);
#pragma unroll
    for (int i = 0; i < 3; i++)
#pragma unroll
        for (int l = 0; l < 3; l++)
            Hm[i * 3 + l] = dot3m(tmp[i * 3 + 0], g_K0[n][0 * 3 + l],
                                  tmp[i * 3 + 1], g_K0[n][1 * 3 + l],
                                  tmp[i * 3 + 2], g_K0[n][2 * 3 + l]);

    const float* dstn = dst + n * HW;
    const float fw = (float)w, fh = (float)h;
    float samp[PS];
    bool mall = true;
    float dsum = 0.f;

    // Fully predicated taps (reference semantics; no branches)
#pragma unroll
    for (int p = 0; p < PS; p++) {
        float cy = fh + (float)(p / 5 - 2);
        float cx = fw + (float)(p % 5 - 2);
        float X0 = dot3f(Hm[0], cx, Hm[1], cy, Hm[2], 1.f);
        float X1 = dot3f(Hm[3], cx, Hm[4], cy, Hm[5], 1.f);
        float z  = dot3f(Hm[6], cx, Hm[7], cy, Hm[8], 1.f);
        float zs = (z != 0.f) ? z : 1.f;
        float xwr = __fdiv_rn(X0, zs);
        float ywr = __fdiv_rn(X1, zs);
        bool ok0 = (z > 0.f);                 // nz<0, dp>0 already hold
        float xw1 = ok0 ? xwr : 0.f;
        float yw1 = ok0 ? ywr : 0.f;
        bool ok = ok0 && (xw1 > 0.f) && (xw1 < (float)(W - 1)) &&
                  (yw1 > 0.f) && (yw1 < (float)(H - 1));
        float xf = ok ? xw1 : 0.f;            // reference where(mask, ., 0)
        float yf = ok ? yw1 : 0.f;
        int lin = (int)yf * W + (int)xf;      // 0 when masked (safe)
        float s  = dstn[lin];
        float sv = ok ? s : 0.f;
        samp[p] = sv;
        mall = mall && ok;
        dsum = __fadd_rn(dsum, sv);
    }

    if (!mall) {
        *vs_out = THR;
        *mb_out = 0;
        return;
    }

    // NCC: stats reloaded (bit-exact), cross reads src directly (interior)
    const float smean = g_smean[pix];
    const float svar  = g_svar[pix];
    float dmean = __fdiv_rn(dsum, 25.f);
    float dvar = 0.f, cross = 0.f;
    const float* srow = src + (h - 2) * W + (w - 2);
#pragma unroll
    for (int p = 0; p < PS; p++) {
        float dc = __fsub_rn(samp[p], dmean);
        dvar  = __fadd_rn(dvar,  __fmul_rn(dc, dc));
        float scv = __fsub_rn(srow[(p / 5) * W + (p % 5)], smean);
        cross = __fadd_rn(cross, __fmul_rn(scv, dc));
    }
    dvar  = __fdiv_rn(dvar, 25.f);
    cross = __fdiv_rn(cross, 25.f);
    float prod = __fmul_rn(svar, dvar);
    *vs_out = (prod > 0.f) ? __fdiv_rn(cross, __fsqrt_rn(prod)) : THR;
    *mb_out = 1;
}

// ---------------------------------------------------------------------------
// Final: per-pixel view combine (sequential sum, identical order), argmax
// over 9 depth taps (strict >, first-max), output assembly.
__global__ void __launch_bounds__(128)
ncc_final_kernel(const float* __restrict__ depth,
                 const float* __restrict__ norm,
                 float* __restrict__ out) {
    using namespace cfg;
    int pix = blockIdx.x * blockDim.x + threadIdx.x;
    if (pix >= HW) return;

    float best = -1e30f;
    int bd = 0;
    bool bmany = false;
#pragma unroll
    for (int dd = 0; dd < DS; dd++) {
        float4 v = g_vs4[dd * HW + pix];
        bool many = g_mb4[dd * HW + pix] != 0u;
        float ssc = __fadd_rn(__fadd_rn(__fadd_rn(v.x, v.y), v.z), v.w);
        float score = many ? __fdiv_rn(ssc, 4.f) : THR;
        if (score > best) { best = score; bd = dd; bmany = many; }
    }

    int h = pix / W;
    int w = pix - h * W;
    int pd = perm_d(bd);
    int pi = pd / 3 - 1;
    int pj = pd % 3 - 1;

    int hd = h + DIL * pi, wd = w + DIL * pj;
    float dp = 0.f;
    if (hd >= 0 && hd < H && wd >= 0 && wd < W) dp = depth[hd * W + wd];

    int hn = h + pi, wn = w + pj;
    float nx = 0.f, ny = 0.f, nz = 0.f;
    if (hn >= 0 && hn < H && wn >= 0 && wn < W) {
        int o = hn * W + wn;
        nx = norm[o];
        ny = norm[HW + o];
        nz = norm[2 * HW + o];
    }

    out[pix]          = __fsub_rn(1.f, best);
    out[HW + pix]     = dp;
    out[2 * HW + pix] = nx;
    out[3 * HW + pix] = ny;
    out[4 * HW + pix] = nz;
    out[5 * HW + pix] = bmany ? 1.f : 0.f;
}

// ---------------------------------------------------------------------------
extern "C" void kernel_launch(void* const* d_in, const int* in_sizes, int n_in,
                              void* d_out, int out_size) {
    const float* src   = (const float*)d_in[0];
    const float* dst   = (const float*)d_in[1];
    const float* Ks    = (const float*)d_in[2];
    const float* Rs    = (const float*)d_in[3];
    const float* Ts    = (const float*)d_in[4];
    const float* depth = (const float*)d_in[5];
    const float* norm  = (const float*)d_in[6];
    float* out = (float*)d_out;

    dim3 gi((cfg::HW + 255) / 256, cfg::DS + 1);
    init_kernel<<<gi, 256>>>(src, Ks, Rs, Ts, depth, norm);
    dim3 gv((cfg::HW + 255) / 256, cfg::DS, cfg::NVIEW);
    ncc_view_kernel<<<gv, 256>>>(src, dst);
    ncc_final_kernel<<<(cfg::HW + 127) / 128, 128>>>(depth, norm, out);
}

// round 16
// speedup vs baseline: 1.1816x; 1.1816x over previous
#include <cuda_runtime.h>

// ---------------------------------------------------------------------------
// NCC plane-sweep forward (B=1, N=4, H=160, W=192, patch 5x5, 9 depth taps,
// depth dilation 2). Arithmetic FROZEN (bit-exact vs reference since R9):
//   PP=K·R: FMA-ascending; Hmat chain: mul+add; tap matvec: FMA-ascending;
//   all divides IEEE div.rn; reductions mul+add; view sum sequential.
// R15 (scheduling only):
//   - REVERT R14 predication: break-based tap loop (work-skipping wins)
//   - keep tap table (dp,nv) from init kernel (1 LDG.128 per thread)
//   - view block = 64 pixels x 4 views (warp stays single-view, 32 consecutive
//     pixels); smem combine writes COMBINED score+many to [HW][12] layout
//   - final kernel reads its pixel's own 48B row: 3 LDG.128 + 3 LDG.32
// ---------------------------------------------------------------------------

namespace cfg {
constexpr int H = 160;
constexpr int W = 192;
constexpr int NVIEW = 4;
constexpr int DS = 9;
constexpr int DIL = 2;
constexpr int PS = 25;
constexpr int HW = H * W;
constexpr float THR = 0.5f;
constexpr int DPAD = 12;      // padded depth-tap row (9 used)
}

__device__ float g_PP[cfg::NVIEW][9];    // K * R
__device__ float g_K0[cfg::NVIEW][9];    // K^-1 (Ks[:, :, 0])
__device__ float g_T[cfg::NVIEW][3];
__device__ float g_smean[cfg::HW];
__device__ float g_svar[cfg::HW];
__device__ float4 g_tap[cfg::DS * cfg::HW];          // (dp, nv0, nv1, nv2)
__device__ float  g_sc[cfg::HW * cfg::DPAD];         // combined score [HW][12]
__device__ unsigned char g_mn[cfg::HW * cfg::DPAD];  // many flag     [HW][12]

__device__ __forceinline__ int perm_d(int d) {
    return (d == 0) ? 4 : (d == 4) ? 0 : d;
}

// Plain mul+add sequential chain (no FMA)
__device__ __forceinline__ float dot3m(float a0, float b0, float a1, float b1,
                                       float a2, float b2) {
    return __fadd_rn(__fadd_rn(__fmul_rn(a0, b0), __fmul_rn(a1, b1)),
                     __fmul_rn(a2, b2));
}

// Ascending FMA chain, zero init
__device__ __forceinline__ float dot3f(float a0, float b0, float a1, float b1,
                                       float a2, float b2) {
    return fmaf(a2, b2, fmaf(a1, b1, __fmul_rn(a0, b0)));
}

// ---------------------------------------------------------------------------
// grid.y == 0 : camera constants (block 0) + per-pixel src stats
// grid.y >= 1 : per-(pix, d=y-1) tap table (dp, nv) with zero padding
__global__ void __launch_bounds__(256)
init_kernel(const float* __restrict__ src,
            const float* __restrict__ Ks,
            const float* __restrict__ Rs,
            const float* __restrict__ Ts,
            const float* __restrict__ depth,
            const float* __restrict__ norm) {
    using namespace cfg;
    int pix = blockIdx.x * blockDim.x + threadIdx.x;

    if (blockIdx.y == 0) {
        if (blockIdx.x == 0 && threadIdx.x < NVIEW) {
            int n = threadIdx.x;
            const float* Ki = Ks + n * 18;       // Ks[0,n,0] = K^-1
            const float* K  = Ks + n * 18 + 9;   // Ks[0,n,1] = K
            const float* R  = Rs + n * 9;
#pragma unroll
            for (int i = 0; i < 3; i++)
#pragma unroll
                for (int j = 0; j < 3; j++)
                    g_PP[n][i * 3 + j] = dot3f(K[i * 3 + 0], R[0 * 3 + j],
                                               K[i * 3 + 1], R[1 * 3 + j],
                                               K[i * 3 + 2], R[2 * 3 + j]);
#pragma unroll
            for (int i = 0; i < 9; i++) g_K0[n][i] = Ki[i];
#pragma unroll
            for (int i = 0; i < 3; i++) g_T[n][i] = Ts[n * 3 + i];
        }
        if (pix >= HW) return;
        int h = pix / W;
        int w = pix - h * W;

        float sp[PS];
        float ssum = 0.f;
#pragma unroll
        for (int p = 0; p < PS; p++) {
            int hh = h + p / 5 - 2, ww = w + p % 5 - 2;
            float v = 0.f;
            if (hh >= 0 && hh < H && ww >= 0 && ww < W) v = src[hh * W + ww];
            sp[p] = v;
            ssum = __fadd_rn(ssum, v);
        }
        float smean = __fdiv_rn(ssum, 25.f);
        float svar = 0.f;
#pragma unroll
        for (int p = 0; p < PS; p++) {
            float scv = __fsub_rn(sp[p], smean);
            svar = __fadd_rn(svar, __fmul_rn(scv, scv));
        }
        g_smean[pix] = smean;
        g_svar[pix]  = __fdiv_rn(svar, 25.f);
        return;
    }

    if (pix >= HW) return;
    const int d = blockIdx.y - 1;
    const int h = pix / W;
    const int w = pix - h * W;
    const int pd = perm_d(d);
    const int pi = pd / 3 - 1;
    const int pj = pd % 3 - 1;

    int hd = h + DIL * pi, wd = w + DIL * pj;
    float dp = 0.f;
    if (hd >= 0 && hd < H && wd >= 0 && wd < W) dp = depth[hd * W + wd];

    int hn = h + pi, wn = w + pj;
    float nv0 = 0.f, nv1 = 0.f, nv2 = 0.f;
    if (hn >= 0 && hn < H && wn >= 0 && wn < W) {
        int o = hn * W + wn;
        nv0 = norm[o];
        nv1 = norm[HW + o];
        nv2 = norm[2 * HW + o];
    }
    g_tap[d * HW + pix] = make_float4(dp, nv0, nv1, nv2);
}

// ---------------------------------------------------------------------------
// Block = 64 pixels x 4 views (tid = n*64 + p: warps are single-view,
// 32 consecutive pixels). grid = (HW/64, DS). In-block 4-view combine.
__global__ void __launch_bounds__(256)
ncc_view_kernel(const float* __restrict__ src,
                const float* __restrict__ dst) {
    using namespace cfg;
    const int p  = threadIdx.x & 63;
    const int n  = threadIdx.x >> 6;
    const int pix = blockIdx.x * 64 + p;
    const int d  = blockIdx.y;
    const int h  = pix / W;
    const int w  = pix - h * W;

    float vsc = THR;
    bool mall = false;

    const float4 tap = g_tap[d * HW + pix];
    const float dp  = tap.x;
    const float nv0 = tap.y, nv1 = tap.z, nv2 = tap.w;

    bool valid = (dp > 0.f) && (nv2 < 0.f) &&
                 (h >= 2) && (h < H - 2) && (w >= 2) && (w < W - 2);

    if (valid) {
        const float dsafe = dp;  // dp > 0 here

        // m = I - (T_i * n_j) / dsafe  (entry-wise IEEE ops)
        float mM[9];
#pragma unroll
        for (int i = 0; i < 3; i++) {
            float Ti = g_T[n][i];
            float q0 = __fdiv_rn(__fmul_rn(Ti, nv0), dsafe);
            float q1 = __fdiv_rn(__fmul_rn(Ti, nv1), dsafe);
            float q2 = __fdiv_rn(__fmul_rn(Ti, nv2), dsafe);
            mM[i * 3 + 0] = __fsub_rn((i == 0) ? 1.f : 0.f, q0);
            mM[i * 3 + 1] = __fsub_rn((i == 1) ? 1.f : 0.f, q1);
            mM[i * 3 + 2] = __fsub_rn((i == 2) ? 1.f : 0.f, q2);
        }
        // tmp = PP @ m ; Hm = tmp @ K0  (mul+add chains)
        float tmp[9], Hm[9];
#pragma unroll
        for (int i = 0; i < 3; i++)
#pragma unroll
            for (int k = 0; k < 3; k++)
                tmp[i * 3 + k] = dot3m(g_PP[n][i * 3 + 0], mM[0 * 3 + k],
                                       g_PP[n][i * 3 + 1], mM[1 * 3 + k],
                                       g_PP[n][i * 3 + 2], mM[2 * 3 + k]);
#pragma unroll
        for (int i = 0; i < 3; i++)
#pragma unroll
            for (int l = 0; l < 3; l++)
                Hm[i * 3 + l] = dot3m(tmp[i * 3 + 0], g_K0[n][0 * 3 + l],
                                      tmp[i * 3 + 1], g_K0[n][1 * 3 + l],
                                      tmp[i * 3 + 2], g_K0[n][2 * 3 + l]);

        const float* dstn = dst + n * HW;
        const float fw = (float)w, fh = (float)h;
        float samp[PS];
        float dsum = 0.f;
        mall = true;

#pragma unroll
        for (int pp = 0; pp < PS; pp++) {
            float cy = fh + (float)(pp / 5 - 2);
            float cx = fw + (float)(pp % 5 - 2);
            float X0 = dot3f(Hm[0], cx, Hm[1], cy, Hm[2], 1.f);
            float X1 = dot3f(Hm[3], cx, Hm[4], cy, Hm[5], 1.f);
            float z  = dot3f(Hm[6], cx, Hm[7], cy, Hm[8], 1.f);
            if (!(z > 0.f)) { mall = false; break; }  // divide results unused
            float xw = __fdiv_rn(X0, z);              // zs == z when z > 0
            float yw = __fdiv_rn(X1, z);
            bool ok = (xw > 0.f) && (xw < (float)(W - 1)) &&
                      (yw > 0.f) && (yw < (float)(H - 1));
            if (!ok) { mall = false; break; }   // rest of this view unused
            float s = dstn[(int)yw * W + (int)xw];
            samp[pp] = s;
            dsum = __fadd_rn(dsum, s);
        }

        if (mall) {
            const float smean = g_smean[pix];
            const float svar  = g_svar[pix];
            float dmean = __fdiv_rn(dsum, 25.f);
            float dvar = 0.f, cross = 0.f;
            const float* srow = src + (h - 2) * W + (w - 2);
#pragma unroll
            for (int pp = 0; pp < PS; pp++) {
                float dc = __fsub_rn(samp[pp], dmean);
                dvar  = __fadd_rn(dvar,  __fmul_rn(dc, dc));
                float scv = __fsub_rn(srow[(pp / 5) * W + (pp % 5)], smean);
                cross = __fadd_rn(cross, __fmul_rn(scv, dc));
            }
            dvar  = __fdiv_rn(dvar, 25.f);
            cross = __fdiv_rn(cross, 25.f);
            float prod = __fmul_rn(svar, dvar);
            vsc = (prod > 0.f) ? __fdiv_rn(cross, __fsqrt_rn(prod)) : THR;
        }
    }

    // in-block 4-view combine (sequential order preserved)
    __shared__ float         s_v[NVIEW][64];
    __shared__ unsigned char s_m[NVIEW][64];
    s_v[n][p] = vsc;
    s_m[n][p] = mall ? (unsigned char)1 : (unsigned char)0;
    __syncthreads();
    if (n == 0) {
        float v0 = s_v[0][p], v1 = s_v[1][p], v2 = s_v[2][p], v3 = s_v[3][p];
        bool many = (s_m[0][p] | s_m[1][p] | s_m[2][p] | s_m[3][p]) != 0;
        float ssc = __fadd_rn(__fadd_rn(__fadd_rn(v0, v1), v2), v3);
        g_sc[pix * DPAD + d] = many ? __fdiv_rn(ssc, 4.f) : THR;
        g_mn[pix * DPAD + d] = many ? (unsigned char)1 : (unsigned char)0;
    }
}

// ---------------------------------------------------------------------------
// Final: per-pixel argmax over 9 depth taps (strict >, first-max), reading
// the pixel's own contiguous 48B score row, then output assembly.
__global__ void __launch_bounds__(128)
ncc_final_kernel(const float* __restrict__ depth,
                 const float* __restrict__ norm,
                 float* __restrict__ out) {
    using namespace cfg;
    int pix = blockIdx.x * blockDim.x + threadIdx.x;
    if (pix >= HW) return;

    const float4* sc4 = reinterpret_cast<const float4*>(g_sc + pix * DPAD);
    float4 a = sc4[0], b = sc4[1], c = sc4[2];
    float s[DS] = {a.x, a.y, a.z, a.w, b.x, b.y, b.z, b.w, c.x};
    const unsigned* mn4 = reinterpret_cast<const unsigned*>(g_mn + pix * DPAD);
    unsigned m0 = mn4[0], m1 = mn4[1], m2 = mn4[2];

    float best = -1e30f;
    int bd = 0;
#pragma unroll
    for (int dd = 0; dd < DS; dd++) {
        if (s[dd] > best) { best = s[dd]; bd = dd; }
    }
    unsigned mword = (bd < 4) ? m0 : (bd < 8) ? m1 : m2;
    bool bmany = ((mword >> ((bd & 3) * 8)) & 0xFFu) != 0;

    int h = pix / W;
    int w = pix - h * W;
    int pd = perm_d(bd);
    int pi = pd / 3 - 1;
    int pj = pd % 3 - 1;

    int hd = h + DIL * pi, wd = w + DIL * pj;
    float dp = 0.f;
    if (hd >= 0 && hd < H && wd >= 0 && wd < W) dp = depth[hd * W + wd];

    int hn = h + pi, wn = w + pj;
    float nx = 0.f, ny = 0.f, nz = 0.f;
    if (hn >= 0 && hn < H && wn >= 0 && wn < W) {
        int o = hn * W + wn;
        nx = norm[o];
        ny = norm[HW + o];
        nz = norm[2 * HW + o];
    }

    out[pix]          = __fsub_rn(1.f, best);
    out[HW + pix]     = dp;
    out[2 * HW + pix] = nx;
    out[3 * HW + pix] = ny;
    out[4 * HW + pix] = nz;
    out[5 * HW + pix] = bmany ? 1.f : 0.f;
}

// ---------------------------------------------------------------------------
extern "C" void kernel_launch(void* const* d_in, const int* in_sizes, int n_in,
                              void* d_out, int out_size) {
    const float* src   = (const float*)d_in[0];
    const float* dst   = (const float*)d_in[1];
    const float* Ks    = (const float*)d_in[2];
    const float* Rs    = (const float*)d_in[3];
    const float* Ts    = (const float*)d_in[4];
    const float* depth = (const float*)d_in[5];
    const float* norm  = (const float*)d_in[6];
    float* out = (float*)d_out;

    dim3 gi((cfg::HW + 255) / 256, cfg::DS + 1);
    init_kernel<<<gi, 256>>>(src, Ks, Rs, Ts, depth, norm);
    dim3 gv(cfg::HW / 64, cfg::DS);
    ncc_view_kernel<<<gv, 256>>>(src, dst);
    ncc_final_kernel<<<(cfg::HW + 127) / 128, 128>>>(depth, norm, out);
}

// round 17
// speedup vs baseline: 1.3079x; 1.1069x over previous
#include <cuda_runtime.h>

// ---------------------------------------------------------------------------
// NCC plane-sweep forward. Arithmetic FROZEN (bit-exact vs reference, R9):
//   PP=K·R FMA-ascending; Hmat chain mul+add; tap matvec FMA-ascending;
//   divides correctly-rounded (CR result unique -> implementation-free);
//   reductions mul+add; view sum sequential.
// R16 (instruction-count reduction, bit-preserving):
//   - CR division via Markstein w/ shared refined reciprocal (mM: 1 rcp for
//     9 divides; per tap: 1 rcp for x & y)
//   - f32x2 packed tap matvec (pairs of taps per instruction; IEEE per lane)
// ---------------------------------------------------------------------------

namespace cfg {
constexpr int H = 160;
constexpr int W = 192;
constexpr int NVIEW = 4;
constexpr int DS = 9;
constexpr int DIL = 2;
constexpr int PS = 25;
constexpr int HW = H * W;
constexpr float THR = 0.5f;
constexpr int DPAD = 12;
}

typedef unsigned long long u64;

__device__ float g_PP[cfg::NVIEW][9];
__device__ float g_K0[cfg::NVIEW][9];
__device__ float g_T[cfg::NVIEW][3];
__device__ float g_smean[cfg::HW];
__device__ float g_svar[cfg::HW];
__device__ float4 g_tap[cfg::DS * cfg::HW];
__device__ float  g_sc[cfg::HW * cfg::DPAD];
__device__ unsigned char g_mn[cfg::HW * cfg::DPAD];

__device__ __forceinline__ int perm_d(int d) {
    return (d == 0) ? 4 : (d == 4) ? 0 : d;
}

__device__ __forceinline__ float dot3m(float a0, float b0, float a1, float b1,
                                       float a2, float b2) {
    return __fadd_rn(__fadd_rn(__fmul_rn(a0, b0), __fmul_rn(a1, b1)),
                     __fmul_rn(a2, b2));
}
__device__ __forceinline__ float dot3f(float a0, float b0, float a1, float b1,
                                       float a2, float b2) {
    return fmaf(a2, b2, fmaf(a1, b1, __fmul_rn(a0, b0)));
}

// ---- correctly-rounded division helpers -----------------------------------
// y = reciprocal refined by two Newton steps: |y - 1/d| < 1 ulp.
__device__ __forceinline__ float rcp2nr(float d) {
    float y;
    asm("rcp.approx.f32 %0, %1;" : "=f"(y) : "f"(d));
    float e = __fmaf_rn(-d, y, 1.0f);
    y = __fmaf_rn(y, e, y);
    e = __fmaf_rn(-d, y, 1.0f);
    y = __fmaf_rn(y, e, y);
    return y;
}
// Markstein final step: correctly-rounded n/d given refined y (normal inputs).
__device__ __forceinline__ float div_cr(float n, float d, float y) {
    float q = __fmul_rn(n, y);
    float r = __fmaf_rn(-d, q, n);
    return __fmaf_rn(r, y, q);
}

// ---- f32x2 packed helpers (sm_103a; IEEE round-to-nearest per lane) --------
__device__ __forceinline__ u64 pk(float lo, float hi) {
    u64 r; asm("mov.b64 %0, {%1, %2};" : "=l"(r) : "f"(lo), "f"(hi)); return r;
}
__device__ __forceinline__ float2 upk(u64 v) {
    float2 r; asm("mov.b64 {%0, %1}, %2;" : "=f"(r.x), "=f"(r.y) : "l"(v));
    return r;
}
__device__ __forceinline__ u64 mul2(u64 a, u64 b) {
    u64 r; asm("mul.rn.f32x2 %0, %1, %2;" : "=l"(r) : "l"(a), "l"(b)); return r;
}
__device__ __forceinline__ u64 add2(u64 a, u64 b) {
    u64 r; asm("add.rn.f32x2 %0, %1, %2;" : "=l"(r) : "l"(a), "l"(b)); return r;
}
__device__ __forceinline__ u64 fma2(u64 a, u64 b, u64 c) {
    u64 r; asm("fma.rn.f32x2 %0, %1, %2, %3;"
               : "=l"(r) : "l"(a), "l"(b), "l"(c)); return r;
}

// ---------------------------------------------------------------------------
__global__ void __launch_bounds__(256)
init_kernel(const float* __restrict__ src,
            const float* __restrict__ Ks,
            const float* __restrict__ Rs,
            const float* __restrict__ Ts,
            const float* __restrict__ depth,
            const float* __restrict__ norm) {
    using namespace cfg;
    int pix = blockIdx.x * blockDim.x + threadIdx.x;

    if (blockIdx.y == 0) {
        if (blockIdx.x == 0 && threadIdx.x < NVIEW) {
            int n = threadIdx.x;
            const float* Ki = Ks + n * 18;
            const float* K  = Ks + n * 18 + 9;
            const float* R  = Rs + n * 9;
#pragma unroll
            for (int i = 0; i < 3; i++)
#pragma unroll
                for (int j = 0; j < 3; j++)
                    g_PP[n][i * 3 + j] = dot3f(K[i * 3 + 0], R[0 * 3 + j],
                                               K[i * 3 + 1], R[1 * 3 + j],
                                               K[i * 3 + 2], R[2 * 3 + j]);
#pragma unroll
            for (int i = 0; i < 9; i++) g_K0[n][i] = Ki[i];
#pragma unroll
            for (int i = 0; i < 3; i++) g_T[n][i] = Ts[n * 3 + i];
        }
        if (pix >= HW) return;
        int h = pix / W;
        int w = pix - h * W;

        float sp[PS];
        float ssum = 0.f;
#pragma unroll
        for (int p = 0; p < PS; p++) {
            int hh = h + p / 5 - 2, ww = w + p % 5 - 2;
            float v = 0.f;
            if (hh >= 0 && hh < H && ww >= 0 && ww < W) v = src[hh * W + ww];
            sp[p] = v;
            ssum = __fadd_rn(ssum, v);
        }
        float smean = __fdiv_rn(ssum, 25.f);
        float svar = 0.f;
#pragma unroll
        for (int p = 0; p < PS; p++) {
            float scv = __fsub_rn(sp[p], smean);
            svar = __fadd_rn(svar, __fmul_rn(scv, scv));
        }
        g_smean[pix] = smean;
        g_svar[pix]  = __fdiv_rn(svar, 25.f);
        return;
    }

    if (pix >= HW) return;
    const int d = blockIdx.y - 1;
    const int h = pix / W;
    const int w = pix - h * W;
    const int pd = perm_d(d);
    const int pi = pd / 3 - 1;
    const int pj = pd % 3 - 1;

    int hd = h + DIL * pi, wd = w + DIL * pj;
    float dp = 0.f;
    if (hd >= 0 && hd < H && wd >= 0 && wd < W) dp = depth[hd * W + wd];

    int hn = h + pi, wn = w + pj;
    float nv0 = 0.f, nv1 = 0.f, nv2 = 0.f;
    if (hn >= 0 && hn < H && wn >= 0 && wn < W) {
        int o = hn * W + wn;
        nv0 = norm[o];
        nv1 = norm[HW + o];
        nv2 = norm[2 * HW + o];
    }
    g_tap[d * HW + pix] = make_float4(dp, nv0, nv1, nv2);
}

// ---------------------------------------------------------------------------
// Per-tap tail: z check, CR divides (shared 1/z), bounds, gather.
__device__ __forceinline__ bool do_tap(float z, float X0, float X1,
                                       const float* __restrict__ dstn,
                                       float& dsum, float* samp, int pp) {
    using namespace cfg;
    if (!(z > 0.f)) return false;
    float y  = rcp2nr(z);
    float xw = div_cr(X0, z, y);
    float yw = div_cr(X1, z, y);
    bool ok = (xw > 0.f) && (xw < (float)(W - 1)) &&
              (yw > 0.f) && (yw < (float)(H - 1));
    if (!ok) return false;
    float s = dstn[(int)yw * W + (int)xw];
    samp[pp] = s;
    dsum = __fadd_rn(dsum, s);
    return true;
}

// Block = 64 pixels x 4 views (tid = n*64 + p). grid = (HW/64, DS).
__global__ void __launch_bounds__(256)
ncc_view_kernel(const float* __restrict__ src,
                const float* __restrict__ dst) {
    using namespace cfg;
    const int p   = threadIdx.x & 63;
    const int n   = threadIdx.x >> 6;
    const int pix = blockIdx.x * 64 + p;
    const int d   = blockIdx.y;
    const int h   = pix / W;
    const int w   = pix - h * W;

    float vsc = THR;
    bool mall = false;

    const float4 tap = g_tap[d * HW + pix];
    const float dp  = tap.x;
    const float nv0 = tap.y, nv1 = tap.z, nv2 = tap.w;

    bool valid = (dp > 0.f) && (nv2 < 0.f) &&
                 (h >= 2) && (h < H - 2) && (w >= 2) && (w < W - 2);

    if (valid) {
        const float dsafe = dp;
        const float ydp = rcp2nr(dsafe);      // shared for all 9 divides

        float mM[9];
#pragma unroll
        for (int i = 0; i < 3; i++) {
            float Ti = g_T[n][i];
            float q0 = div_cr(__fmul_rn(Ti, nv0), dsafe, ydp);
            float q1 = div_cr(__fmul_rn(Ti, nv1), dsafe, ydp);
            float q2 = div_cr(__fmul_rn(Ti, nv2), dsafe, ydp);
            mM[i * 3 + 0] = __fsub_rn((i == 0) ? 1.f : 0.f, q0);
            mM[i * 3 + 1] = __fsub_rn((i == 1) ? 1.f : 0.f, q1);
            mM[i * 3 + 2] = __fsub_rn((i == 2) ? 1.f : 0.f, q2);
        }
        float tmp[9], Hm[9];
#pragma unroll
        for (int i = 0; i < 3; i++)
#pragma unroll
            for (int k = 0; k < 3; k++)
                tmp[i * 3 + k] = dot3m(g_PP[n][i * 3 + 0], mM[0 * 3 + k],
                                       g_PP[n][i * 3 + 1], mM[1 * 3 + k],
                                       g_PP[n][i * 3 + 2], mM[2 * 3 + k]);
#pragma unroll
        for (int i = 0; i < 3; i++)
#pragma unroll
            for (int l = 0; l < 3; l++)
                Hm[i * 3 + l] = dot3m(tmp[i * 3 + 0], g_K0[n][0 * 3 + l],
                                      tmp[i * 3 + 1], g_K0[n][1 * 3 + l],
                                      tmp[i * 3 + 2], g_K0[n][2 * 3 + l]);

        const float* dstn = dst + n * HW;
        const float fw = (float)w, fh = (float)h;
        float samp[PS];
        float dsum = 0.f;
        mall = true;

        // packed per-view constants (duplicated lanes)
        const u64 fw2 = pk(fw, fw), fh2 = pk(fh, fh);
        const u64 H00 = pk(Hm[0], Hm[0]), H11 = pk(Hm[1], Hm[1]),
                  H22 = pk(Hm[2], Hm[2]);
        const u64 H33 = pk(Hm[3], Hm[3]), H44 = pk(Hm[4], Hm[4]),
                  H55 = pk(Hm[5], Hm[5]);
        const u64 H66 = pk(Hm[6], Hm[6]), H77 = pk(Hm[7], Hm[7]),
                  H88 = pk(Hm[8], Hm[8]);

#pragma unroll
        for (int pr = 0; pr < 13; pr++) {
            if (!mall) break;
            const int p0 = 2 * pr;
            const int p1 = (p0 + 1 < PS) ? p0 + 1 : p0;   // clamp (lane unused)
            // coords: cx = fw + (j-2), cy = fh + (i-2)  (add.rn per lane)
            const u64 cxx = add2(fw2, pk((float)(p0 % 5 - 2),
                                         (float)(p1 % 5 - 2)));
            const u64 cyy = add2(fh2, pk((float)(p0 / 5 - 2),
                                         (float)(p1 / 5 - 2)));
            // X = Hm_a*cx + Hm_b*cy + Hm_c   (mul, fma, add per lane — same
            // rounding as scalar chain: fma(c,1,t) == add.rn(c,t))
            const u64 X0p = add2(H22, fma2(H11, cyy, mul2(H00, cxx)));
            const u64 X1p = add2(H55, fma2(H44, cyy, mul2(H33, cxx)));
            const u64 Zp  = add2(H88, fma2(H77, cyy, mul2(H66, cxx)));
            float2 z2  = upk(Zp);
            float2 x02 = upk(X0p);
            float2 x12 = upk(X1p);
            if (!do_tap(z2.x, x02.x, x12.x, dstn, dsum, samp, p0)) {
                mall = false; break;
            }
            if (p0 + 1 < PS) {
                if (!do_tap(z2.y, x02.y, x12.y, dstn, dsum, samp, p0 + 1)) {
                    mall = false; break;
                }
            }
        }

        if (mall) {
            const float smean = g_smean[pix];
            const float svar  = g_svar[pix];
            float dmean = __fdiv_rn(dsum, 25.f);
            float dvar = 0.f, cross = 0.f;
            const float* srow = src + (h - 2) * W + (w - 2);
#pragma unroll
            for (int pp = 0; pp < PS; pp++) {
                float dc = __fsub_rn(samp[pp], dmean);
                dvar  = __fadd_rn(dvar,  __fmul_rn(dc, dc));
                float scv = __fsub_rn(srow[(pp / 5) * W + (pp % 5)], smean);
                cross = __fadd_rn(cross, __fmul_rn(scv, dc));
            }
            dvar  = __fdiv_rn(dvar, 25.f);
            cross = __fdiv_rn(cross, 25.f);
            float prod = __fmul_rn(svar, dvar);
            vsc = (prod > 0.f) ? __fdiv_rn(cross, __fsqrt_rn(prod)) : THR;
        }
    }

    __shared__ float         s_v[NVIEW][64];
    __shared__ unsigned char s_m[NVIEW][64];
    s_v[n][p] = vsc;
    s_m[n][p] = mall ? (unsigned char)1 : (unsigned char)0;
    __syncthreads();
    if (n == 0) {
        float v0 = s_v[0][p], v1 = s_v[1][p], v2 = s_v[2][p], v3 = s_v[3][p];
        bool many = (s_m[0][p] | s_m[1][p] | s_m[2][p] | s_m[3][p]) != 0;
        float ssc = __fadd_rn(__fadd_rn(__fadd_rn(v0, v1), v2), v3);
        g_sc[pix * DPAD + d] = many ? __fdiv_rn(ssc, 4.f) : THR;
        g_mn[pix * DPAD + d] = many ? (unsigned char)1 : (unsigned char)0;
    }
}

// ---------------------------------------------------------------------------
__global__ void __launch_bounds__(128)
ncc_final_kernel(const float* __restrict__ depth,
                 const float* __restrict__ norm,
                 float* __restrict__ out) {
    using namespace cfg;
    int pix = blockIdx.x * blockDim.x + threadIdx.x;
    if (pix >= HW) return;

    const float4* sc4 = reinterpret_cast<const float4*>(g_sc + pix * DPAD);
    float4 a = sc4[0], b = sc4[1], c = sc4[2];
    float s[DS] = {a.x, a.y, a.z, a.w, b.x, b.y, b.z, b.w, c.x};
    const unsigned* mn4 = reinterpret_cast<const unsigned*>(g_mn + pix * DPAD);
    unsigned m0 = mn4[0], m1 = mn4[1], m2 = mn4[2];

    float best = -1e30f;
    int bd = 0;
#pragma unroll
    for (int dd = 0; dd < DS; dd++) {
        if (s[dd] > best) { best = s[dd]; bd = dd; }
    }
    unsigned mword = (bd < 4) ? m0 : (bd < 8) ? m1 : m2;
    bool bmany = ((mword >> ((bd & 3) * 8)) & 0xFFu) != 0;

    int h = pix / W;
    int w = pix - h * W;
    int pd = perm_d(bd);
    int pi = pd / 3 - 1;
    int pj = pd % 3 - 1;

    int hd = h + DIL * pi, wd = w + DIL * pj;
    float dp = 0.f;
    if (hd >= 0 && hd < H && wd >= 0 && wd < W) dp = depth[hd * W + wd];

    int hn = h + pi, wn = w + pj;
    float nx = 0.f, ny = 0.f, nz = 0.f;
    if (hn >= 0 && hn < H && wn >= 0 && wn < W) {
        int o = hn * W + wn;
        nx = norm[o];
        ny = norm[HW + o];
        nz = norm[2 * HW + o];
    }

    out[pix]          = __fsub_rn(1.f, best);
    out[HW + pix]     = dp;
    out[2 * HW + pix] = nx;
    out[3 * HW + pix] = ny;
    out[4 * HW + pix] = nz;
    out[5 * HW + pix] = bmany ? 1.f : 0.f;
}

// ---------------------------------------------------------------------------
extern "C" void kernel_launch(void* const* d_in, const int* in_sizes, int n_in,
                              void* d_out, int out_size) {
    const float* src   = (const float*)d_in[0];
    const float* dst   = (const float*)d_in[1];
    const float* Ks    = (const float*)d_in[2];
    const float* Rs    = (const float*)d_in[3];
    const float* Ts    = (const float*)d_in[4];
    const float* depth = (const float*)d_in[5];
    const float* norm  = (const float*)d_in[6];
    float* out = (float*)d_out;

    dim3 gi((cfg::HW + 255) / 256, cfg::DS + 1);
    init_kernel<<<gi, 256>>>(src, Ks, Rs, Ts, depth, norm);
    dim3 gv(cfg::HW / 64, cfg::DS);
    ncc_view_kernel<<<gv, 256>>>(src, dst);
    ncc_final_kernel<<<(cfg::HW + 127) / 128, 128>>>(depth, norm, out);
}